// round 16
// baseline (speedup 1.0000x reference)
#include <cuda_runtime.h>
#include <cuda_bf16.h>
#include <math.h>
#include <cstdint>

#define B_ 256
#define NQ_ 8
#define NL_ 2
#define NCLS_ 5

// ---------------- scratch buffers (bf16 intermediates) ----------------
__device__ unsigned       g_buf1[B_ * 32 * 1500];   // conv1 out: bf16, stride 3000 halfs
__device__ unsigned short g_buf2[B_ * 64 * 752];    // conv2+pool out: stride 752, len 750
__device__ unsigned short g_buf3[B_ * 128 * 188];   // conv3+pool out: stride 188, len 187
__device__ float g_feat[B_ * 128];                  // conv4 sums (atomic)
__device__ float g_ang[B_ * NQ_];                   // angles

// fragment-ordered bf16 weights: [(mt*KS2+ks2)*32+lane] -> uint4 {a0,a1,a2,a3}
__device__ uint4 g_ap1[2 * 2 * 32];
__device__ uint4 g_ap2[4 * 16 * 32];
__device__ uint4 g_ap3[8 * 32 * 32];
__device__ uint4 g_ap4[8 * 64 * 32];
__device__ float g_bb1[32], g_bb2[64], g_bb3[128], g_bb4[128];

// ---------------- helpers ----------------
__device__ __forceinline__ unsigned pk_bf16(float lo, float hi) {
    unsigned r;
    asm("cvt.rn.bf16x2.f32 %0,%1,%2;" : "=r"(r) : "f"(hi), "f"(lo));
    return r;
}

__device__ __forceinline__ unsigned ldw(const unsigned short* row, int W, int Lh) {
    int h0 = 2 * W;
    if (W >= 0 && h0 + 1 < Lh) return ((const unsigned*)row)[W];
    unsigned lo = (h0 >= 0 && h0 < Lh) ? row[h0] : 0u;
    unsigned hi = (h0 + 1 >= 0 && h0 + 1 < Lh) ? row[h0 + 1] : 0u;
    return lo | (hi << 16);
}

__device__ __forceinline__ void mma_bf16(float* d, const uint4& a,
                                         unsigned b0, unsigned b1)
{
    asm volatile(
        "mma.sync.aligned.m16n8k16.row.col.f32.bf16.bf16.f32 "
        "{%0,%1,%2,%3},{%4,%5,%6,%7},{%8,%9},{%0,%1,%2,%3};"
        : "+f"(d[0]), "+f"(d[1]), "+f"(d[2]), "+f"(d[3])
        : "r"(a.x), "r"(a.y), "r"(a.z), "r"(a.w), "r"(b0), "r"(b1));
}

// ---------------- prepack: BN-fold, bf16, fragment order ----------------
__device__ __forceinline__ float wget(const float* w, int co, int ci, int k,
                                      int CIN, float sc) {
    return (k < 7) ? w[(co * CIN + ci) * 7 + k] * sc : 0.0f;
}

__device__ void prep_one(const float* w, const float* cb, const float* bng,
                         const float* bnb, uint4* ap, float* bbo,
                         int CIN, int COUT, int idx)
{
    const float inv = rsqrtf(1.0f + 1e-5f);
    int KS2 = CIN / 2;
    int total = (COUT / 16) * KS2 * 32;
    if (idx < total) {
        int lane = idx & 31;
        int t = idx >> 5;
        int ks2 = t % KS2;
        int mt = t / KS2;
        int r = lane >> 2;
        int c = lane & 3;
        int co = mt * 16 + r;
        int ci0 = 2 * ks2;
        int ci1 = ci0 + 1;
        int k0 = 2 * c;
        int k1 = 2 * c + 1;
        float sc0 = bng[co] * inv;
        float sc8 = bng[co + 8] * inv;
        uint4 a;
        a.x = pk_bf16(wget(w, co,     ci0, k0, CIN, sc0), wget(w, co,     ci0, k1, CIN, sc0));
        a.y = pk_bf16(wget(w, co + 8, ci0, k0, CIN, sc8), wget(w, co + 8, ci0, k1, CIN, sc8));
        a.z = pk_bf16(wget(w, co,     ci1, k0, CIN, sc0), wget(w, co,     ci1, k1, CIN, sc0));
        a.w = pk_bf16(wget(w, co + 8, ci1, k0, CIN, sc8), wget(w, co + 8, ci1, k1, CIN, sc8));
        ap[idx] = a;
    }
    if (idx < COUT) {
        float sc = bng[idx] * inv;
        bbo[idx] = cb[idx] * sc + bnb[idx];
    }
}

__global__ void prep_all(
    const float* w1, const float* cb1, const float* g1, const float* be1,
    const float* w2, const float* cb2, const float* g2, const float* be2,
    const float* w3, const float* cb3, const float* g3, const float* be3,
    const float* w4, const float* cb4, const float* g4, const float* be4,
    uint4* ap1, float* bb1, uint4* ap2, float* bb2,
    uint4* ap3, float* bb3, uint4* ap4, float* bb4, float* feat)
{
    int idx = blockIdx.x * blockDim.x + threadIdx.x;
    prep_one(w1, cb1, g1, be1, ap1, bb1, 4, 32, idx);
    prep_one(w2, cb2, g2, be2, ap2, bb2, 32, 64, idx);
    prep_one(w3, cb3, g3, be3, ap3, bb3, 64, 128, idx);
    prep_one(w4, cb4, g4, be4, ap4, bb4, 128, 128, idx);
    if (idx < B_ * 128) feat[idx] = 0.0f;
}

// ---------------- shared tile producer (dual-copy layout) ------------
// sw row ci: [copy0: words 0..68 (even pairs)][copy1: words 72..140 (shift 1)]
template<int CIN, bool F32IN, int NWARPS>
__device__ __forceinline__ void load_tile(
    unsigned* sw, const void* in_, int b, int tile0, int Lh, int LSTRin,
    int wid, int lane)
{
    constexpr int RS = 144;
    const int base = tile0 - 4;
    const bool interior = (base >= 0) && (base + 139 < Lh);

    if (F32IN) {
        const float* inb = (const float*)in_ + (size_t)b * CIN * LSTRin;
        for (int ci = wid; ci < CIN; ci += NWARPS) {
            const float* row = inb + ci * LSTRin;
            unsigned* d = sw + ci * RS;
            if (interior) {
                for (int j = lane; j < 69; j += 32) {
                    int g = base + 2 * j;
                    float2 v = *(const float2*)(row + g);
                    float x2 = row[g + 2];
                    d[j]      = pk_bf16(v.x, v.y);
                    d[72 + j] = pk_bf16(v.y, x2);
                }
            } else {
                for (int j = lane; j < 69; j += 32) {
                    int g = base + 2 * j;
                    float x0 = (g >= 0 && g < Lh) ? row[g] : 0.f;
                    float x1 = (g + 1 >= 0 && g + 1 < Lh) ? row[g + 1] : 0.f;
                    float x2 = (g + 2 >= 0 && g + 2 < Lh) ? row[g + 2] : 0.f;
                    d[j]      = pk_bf16(x0, x1);
                    d[72 + j] = pk_bf16(x1, x2);
                }
            }
        }
    } else {
        const unsigned short* inb = (const unsigned short*)in_ + (size_t)b * CIN * LSTRin;
        for (int ci = wid; ci < CIN; ci += NWARPS) {
            const unsigned short* row = inb + ci * LSTRin;
            unsigned* d = sw + ci * RS;
            if (interior) {
                const unsigned* rw = (const unsigned*)row + (base >> 1);
                for (int j = lane; j < 69; j += 32) {
                    unsigned wa = rw[j];
                    unsigned wb = rw[j + 1];
                    d[j]      = wa;
                    d[72 + j] = (wa >> 16) | (wb << 16);
                }
            } else {
                const int W0 = base >> 1;
                for (int j = lane; j < 69; j += 32) {
                    unsigned wa = ldw(row, W0 + j, Lh);
                    unsigned wb = ldw(row, W0 + j + 1, Lh);
                    d[j]      = wa;
                    d[72 + j] = (wa >> 16) | (wb << 16);
                }
            }
        }
    }
}

// ---------------- conv1d(k=7,pad=3)+BN+ReLU(+maxpool4), bf16 implicit GEMM ---
// NT threads, 2 blocks/SM. MT m-tiles per warp, A prefetch, LDS.32 B frags.
template<int CIN, int COUT, int MT, int MODE, bool F32IN, int NT>
__global__ __launch_bounds__(NT, 2) void conv_mma(
    const uint4* __restrict__ Ap, const float* __restrict__ bb,
    const void* __restrict__ in_, void* __restrict__ out_,
    int Lh, int LSTRin, int Lout, int LSTRout)
{
    constexpr int NWARPS = NT / 32;
    constexpr int MW  = COUT / (16 * MT);
    constexpr int NG  = NWARPS / MW;
    constexpr int NSW = 16 / NG;
    constexpr int KS2 = CIN / 2;
    constexpr int RS  = 144;
    extern __shared__ unsigned sw[];

    const int b = blockIdx.y;
    const int tile0 = blockIdx.x * 128;
    const int tid = threadIdx.x;
    const int wid = tid >> 5;
    const int lane = tid & 31;

    load_tile<CIN, F32IN, NWARPS>(sw, in_, b, tile0, Lh, LSTRin, wid, lane);
    __syncthreads();

    const int mw = wid % MW;
    const int ng = wid / MW;
    const int ng_off = ng * (NSW * 8);
    const int gid = lane >> 2;
    const int tid4 = lane & 3;
    const int h0 = ng_off + gid + 2 * tid4 + 1;
    const int off0 = (h0 >> 1) + ((h0 & 1) ? 72 : 0);

    float acc[MT][NSW][4] = {};
    const uint4* A[MT];
    uint4 a[MT];
    uint4 nx[MT];
    #pragma unroll
    for (int m = 0; m < MT; m++) {
        A[m] = Ap + (size_t)((mw * MT + m) * KS2) * 32 + lane;
        a[m] = A[m][0];
    }

    for (int ks2 = 0; ks2 < KS2; ks2++) {
        const int nk = (ks2 + 1 < KS2) ? ks2 + 1 : ks2;
        #pragma unroll
        for (int m = 0; m < MT; m++) nx[m] = A[m][nk * 32];
        const unsigned* s0 = sw + (2 * ks2) * RS + off0;
        #pragma unroll
        for (int ns = 0; ns < NSW; ns++) {
            unsigned b0 = s0[ns * 4];
            unsigned b1 = s0[RS + ns * 4];
            #pragma unroll
            for (int m = 0; m < MT; m++) mma_bf16(acc[m][ns], a[m], b0, b1);
        }
        #pragma unroll
        for (int m = 0; m < MT; m++) a[m] = nx[m];
    }

    #pragma unroll
    for (int m = 0; m < MT; m++) {
        const int mt = mw * MT + m;
        const int co0 = mt * 16 + gid;
        const int co1 = co0 + 8;
        const float bv0 = bb[co0];
        const float bv1 = bb[co1];
        #pragma unroll
        for (int ns = 0; ns < NSW; ns++) {
            int pos = tile0 + ng_off + ns * 8 + 2 * tid4;
            if (MODE == 0) {
                if (pos < Lout) {
                    float y0 = fmaxf(acc[m][ns][0] + bv0, 0.f);
                    float y1 = fmaxf(acc[m][ns][1] + bv0, 0.f);
                    float y2 = fmaxf(acc[m][ns][2] + bv1, 0.f);
                    float y3 = fmaxf(acc[m][ns][3] + bv1, 0.f);
                    unsigned* ow = (unsigned*)out_;
                    ow[((size_t)b * COUT + co0) * (LSTRout >> 1) + (pos >> 1)] = pk_bf16(y0, y1);
                    ow[((size_t)b * COUT + co1) * (LSTRout >> 1) + (pos >> 1)] = pk_bf16(y2, y3);
                }
            } else {
                float m0 = fmaxf(fmaxf(acc[m][ns][0], acc[m][ns][1]) + bv0, 0.f);
                float m1 = fmaxf(fmaxf(acc[m][ns][2], acc[m][ns][3]) + bv1, 0.f);
                m0 = fmaxf(m0, __shfl_xor_sync(0xffffffffu, m0, 1));
                m1 = fmaxf(m1, __shfl_xor_sync(0xffffffffu, m1, 1));
                if (!(lane & 1)) {
                    int pi = ((tile0 + ng_off + ns * 8) >> 2) + (tid4 >> 1);
                    if (pi < Lout) {
                        unsigned short* oh = (unsigned short*)out_;
                        __nv_bfloat16 h0b = __float2bfloat16_rn(m0);
                        __nv_bfloat16 h1b = __float2bfloat16_rn(m1);
                        oh[((size_t)b * COUT + co0) * LSTRout + pi] = *(unsigned short*)&h0b;
                        oh[((size_t)b * COUT + co1) * LSTRout + pi] = *(unsigned short*)&h1b;
                    }
                }
            }
        }
    }
}

// ---------------- conv4 + BN + ReLU + mean (round-6 config: 256 thr) ---------
__global__ __launch_bounds__(256, 2) void conv4_mma_mean(
    const uint4* __restrict__ Ap, const float* __restrict__ bb,
    const unsigned short* __restrict__ in, float* __restrict__ feat)
{
    constexpr int CIN = 128, KS2 = 64, NSW = 8;
    constexpr int Lc = 187, LSTR = 188, RS = 144;
    extern __shared__ unsigned sw[];

    const int b = blockIdx.y;
    const int tile0 = blockIdx.x * 128;
    const int tid = threadIdx.x;
    const int wid = tid >> 5;
    const int lane = tid & 31;

    load_tile<CIN, false, 8>(sw, in, b, tile0, Lc, LSTR, wid, lane);
    __syncthreads();

    const int mw = wid % 4;
    const int ng = wid / 4;
    const int mt0 = mw * 2;
    const int mt1 = mt0 + 1;
    const int ng_off = ng * (NSW * 8);
    const int gid = lane >> 2;
    const int tid4 = lane & 3;
    const int h0 = ng_off + gid + 2 * tid4 + 1;
    const int off0 = (h0 >> 1) + ((h0 & 1) ? 72 : 0);

    float acc[2][NSW][4] = {};
    const uint4* A0 = Ap + (size_t)(mt0 * KS2) * 32 + lane;
    const uint4* A1 = Ap + (size_t)(mt1 * KS2) * 32 + lane;
    uint4 a0 = A0[0];
    uint4 a1 = A1[0];

    for (int ks2 = 0; ks2 < KS2; ks2++) {
        const int nk = (ks2 + 1 < KS2) ? ks2 + 1 : ks2;
        uint4 n0 = A0[nk * 32];
        uint4 n1 = A1[nk * 32];
        const unsigned* s0 = sw + (2 * ks2) * RS + off0;
        #pragma unroll
        for (int ns = 0; ns < NSW; ns++) {
            unsigned b0 = s0[ns * 4];
            unsigned b1 = s0[RS + ns * 4];
            mma_bf16(acc[0][ns], a0, b0, b1);
            mma_bf16(acc[1][ns], a1, b0, b1);
        }
        a0 = n0;
        a1 = n1;
    }

    #pragma unroll
    for (int m = 0; m < 2; m++) {
        const int mt = (m == 0) ? mt0 : mt1;
        const int co0 = mt * 16 + gid;
        const int co1 = co0 + 8;
        const float bv0 = bb[co0];
        const float bv1 = bb[co1];
        float s0 = 0.f, s1 = 0.f;
        #pragma unroll
        for (int ns = 0; ns < NSW; ns++) {
            int pos = tile0 + ng_off + ns * 8 + 2 * tid4;
            if (pos < Lc) {
                s0 += fmaxf(acc[m][ns][0] + bv0, 0.f);
                s1 += fmaxf(acc[m][ns][2] + bv1, 0.f);
            }
            if (pos + 1 < Lc) {
                s0 += fmaxf(acc[m][ns][1] + bv0, 0.f);
                s1 += fmaxf(acc[m][ns][3] + bv1, 0.f);
            }
        }
        s0 += __shfl_xor_sync(0xffffffffu, s0, 1);
        s0 += __shfl_xor_sync(0xffffffffu, s0, 2);
        s1 += __shfl_xor_sync(0xffffffffu, s1, 1);
        s1 += __shfl_xor_sync(0xffffffffu, s1, 2);
        if ((lane & 3) == 0) {
            atomicAdd(feat + b * 128 + co0, s0);
            atomicAdd(feat + b * 128 + co1, s1);
        }
    }
}

// ---------------- fc(128->128)+relu, ang(128->8), angles = pi*tanh ----------
__global__ void head_kernel(const float* __restrict__ feat,
                            const float* __restrict__ fcw, const float* __restrict__ fcb,
                            const float* __restrict__ angw, const float* __restrict__ angb,
                            float* __restrict__ ang)
{
    int b = blockIdx.x;
    int tid = threadIdx.x;   // 128 threads
    __shared__ float f[128];
    __shared__ float h[128];
    f[tid] = feat[b * 128 + tid] * (1.0f / 187.0f);
    __syncthreads();
    float a = fcb[tid];
    const float* wr = fcw + tid * 128;
    #pragma unroll 8
    for (int k = 0; k < 128; k++) a = fmaf(wr[k], f[k], a);
    h[tid] = fmaxf(a, 0.f);
    __syncthreads();
    if (tid < NQ_) {
        float r = angb[tid];
        const float* ar = angw + tid * 128;
        #pragma unroll 8
        for (int k = 0; k < 128; k++) r = fmaf(ar[k], h[k], r);
        ang[b * NQ_ + tid] = 3.14159265358979323846f * tanhf(r);
    }
}

// ---------------- 8-qubit statevector sim + PauliZ + MLP head ----------------
__device__ __forceinline__ float2 cmul(float2 a, float2 b) {
    return make_float2(a.x * b.x - a.y * b.y, a.x * b.y + a.y * b.x);
}
__device__ __forceinline__ float2 cadd(float2 a, float2 b) {
    return make_float2(a.x + b.x, a.y + b.y);
}

__global__ void qsim_kernel(const float* __restrict__ ang, const float* __restrict__ qw,
                            const float* __restrict__ h1w, const float* __restrict__ h1b,
                            const float* __restrict__ h2w, const float* __restrict__ h2b,
                            float* __restrict__ out)
{
    int b = blockIdx.x;
    int i = threadIdx.x;   // 256 threads
    __shared__ float2 st[256];
    st[i] = make_float2(i == 0 ? 1.f : 0.f, 0.f);
    __syncthreads();

    for (int wq = 0; wq < NQ_; wq++) {
        int m = 1 << (7 - wq);
        float a = 0.5f * ang[b * NQ_ + wq];
        float c = cosf(a);
        float s = sinf(a);
        if ((i & m) == 0) {
            float2 a0 = st[i];
            float2 a1 = st[i | m];
            st[i]     = make_float2(c * a0.x - s * a1.x, c * a0.y - s * a1.y);
            st[i | m] = make_float2(s * a0.x + c * a1.x, s * a0.y + c * a1.y);
        }
        __syncthreads();
    }

    for (int l = 0; l < NL_; l++) {
        for (int wq = 0; wq < NQ_; wq++) {
            int m = 1 << (7 - wq);
            const float* p = qw + (l * NQ_ + wq) * 3;
            float phi = p[0];
            float th = p[1];
            float om = p[2];
            float cm = cosf(0.5f * th);
            float sm = sinf(0.5f * th);
            float hpo = 0.5f * (phi + om);
            float hpm = 0.5f * (phi - om);
            float2 m00 = make_float2( cm * cosf(hpo), -cm * sinf(hpo));
            float2 m01 = make_float2(-sm * cosf(hpm), -sm * sinf(hpm));
            float2 m10 = make_float2( sm * cosf(hpm), -sm * sinf(hpm));
            float2 m11 = make_float2( cm * cosf(hpo),  cm * sinf(hpo));
            if ((i & m) == 0) {
                float2 a0 = st[i];
                float2 a1 = st[i | m];
                st[i]     = cadd(cmul(m00, a0), cmul(m01, a1));
                st[i | m] = cadd(cmul(m10, a0), cmul(m11, a1));
            }
            __syncthreads();
        }
        int r = (l % (NQ_ - 1)) + 1;
        for (int q = 0; q < NQ_; q++) {
            int cq = q;
            int tq = (q + r) & 7;
            int mc = 1 << (7 - cq);
            int mt = 1 << (7 - tq);
            if ((i & mc) && !(i & mt)) {
                float2 tmp = st[i];
                st[i] = st[i | mt];
                st[i | mt] = tmp;
            }
            __syncthreads();
        }
    }

    float pv = st[i].x * st[i].x + st[i].y * st[i].y;
    __shared__ float zpart[8][8];
    int warp = i >> 5;
    int lane = i & 31;
    #pragma unroll
    for (int wq = 0; wq < NQ_; wq++) {
        float v = ((i >> (7 - wq)) & 1) ? -pv : pv;
        #pragma unroll
        for (int o = 16; o; o >>= 1) v += __shfl_down_sync(0xffffffffu, v, o);
        if (lane == 0) zpart[warp][wq] = v;
    }
    __syncthreads();

    __shared__ float z[NQ_];
    if (i < NQ_) {
        float s = 0.f;
        #pragma unroll
        for (int w = 0; w < 8; w++) s += zpart[w][i];
        z[i] = s;
    }
    __syncthreads();

    __shared__ float h1[64];
    if (i < 64) {
        float a = h1b[i];
        #pragma unroll
        for (int k = 0; k < NQ_; k++) a = fmaf(h1w[i * NQ_ + k], z[k], a);
        h1[i] = fmaxf(a, 0.f);
    }
    __syncthreads();

    if (i < NCLS_) {
        float a = h2b[i];
        #pragma unroll 8
        for (int k = 0; k < 64; k++) a = fmaf(h2w[i * 64 + k], h1[k], a);
        out[b * NCLS_ + i] = a;
    }
}

// ---------------- launch ----------------
extern "C" void kernel_launch(void* const* d_in, const int* in_sizes, int n_in,
                              void* d_out, int out_size)
{
    const float* x       = (const float*)d_in[0];
    const float* conv1_w = (const float*)d_in[1];
    const float* conv1_b = (const float*)d_in[2];
    const float* bn1_g   = (const float*)d_in[3];
    const float* bn1_b   = (const float*)d_in[4];
    const float* conv2_w = (const float*)d_in[5];
    const float* conv2_b = (const float*)d_in[6];
    const float* bn2_g   = (const float*)d_in[7];
    const float* bn2_b   = (const float*)d_in[8];
    const float* conv3_w = (const float*)d_in[9];
    const float* conv3_b = (const float*)d_in[10];
    const float* bn3_g   = (const float*)d_in[11];
    const float* bn3_b   = (const float*)d_in[12];
    const float* conv4_w = (const float*)d_in[13];
    const float* conv4_b = (const float*)d_in[14];
    const float* bn4_g   = (const float*)d_in[15];
    const float* bn4_b   = (const float*)d_in[16];
    const float* fc_w    = (const float*)d_in[17];
    const float* fc_b    = (const float*)d_in[18];
    const float* ang_w   = (const float*)d_in[19];
    const float* ang_b   = (const float*)d_in[20];
    const float* qw      = (const float*)d_in[21];
    const float* h1_w    = (const float*)d_in[22];
    const float* h1_b    = (const float*)d_in[23];
    const float* h2_w    = (const float*)d_in[24];
    const float* h2_b    = (const float*)d_in[25];
    float* out = (float*)d_out;

    void* pv = 0;
    cudaGetSymbolAddress(&pv, g_buf1);  unsigned* b1 = (unsigned*)pv;
    cudaGetSymbolAddress(&pv, g_buf2);  unsigned short* b2 = (unsigned short*)pv;
    cudaGetSymbolAddress(&pv, g_buf3);  unsigned short* b3 = (unsigned short*)pv;
    cudaGetSymbolAddress(&pv, g_feat);  float* feat = (float*)pv;
    cudaGetSymbolAddress(&pv, g_ang);   float* ang = (float*)pv;
    cudaGetSymbolAddress(&pv, g_ap1);   uint4* ap1 = (uint4*)pv;
    cudaGetSymbolAddress(&pv, g_ap2);   uint4* ap2 = (uint4*)pv;
    cudaGetSymbolAddress(&pv, g_ap3);   uint4* ap3 = (uint4*)pv;
    cudaGetSymbolAddress(&pv, g_ap4);   uint4* ap4 = (uint4*)pv;
    cudaGetSymbolAddress(&pv, g_bb1);   float* bb1 = (float*)pv;
    cudaGetSymbolAddress(&pv, g_bb2);   float* bb2 = (float*)pv;
    cudaGetSymbolAddress(&pv, g_bb3);   float* bb3 = (float*)pv;
    cudaGetSymbolAddress(&pv, g_bb4);   float* bb4 = (float*)pv;

    prep_all<<<128, 256>>>(
        conv1_w, conv1_b, bn1_g, bn1_b, conv2_w, conv2_b, bn2_g, bn2_b,
        conv3_w, conv3_b, bn3_g, bn3_b, conv4_w, conv4_b, bn4_g, bn4_b,
        ap1, bb1, ap2, bb2, ap3, bb3, ap4, bb4, feat);

    size_t sm1 = (size_t)4   * 144 * 4;
    size_t sm2 = (size_t)32  * 144 * 4;
    size_t sm3 = (size_t)64  * 144 * 4;   // 36864
    size_t sm4 = (size_t)128 * 144 * 4;   // 73728 > 48KB

    cudaFuncSetAttribute(conv4_mma_mean,
                         cudaFuncAttributeMaxDynamicSharedMemorySize, (int)sm4);

    // conv1: (B,4,3000) fp32 -> (B,32,3000) bf16 (256 thr, MT=2; round-6 config)
    conv_mma<4, 32, 2, 0, true, 256><<<dim3(24, B_), 256, sm1>>>(
        ap1, bb1, x, b1, 3000, 3000, 3000, 3000);
    // conv2 + pool4 -> (B,64,750) bf16 stride 752 (512 thr, MT=4: 2 LDS : 8 mma)
    conv_mma<32, 64, 4, 4, false, 512><<<dim3(24, B_), 512, sm2>>>(
        ap2, bb2, b1, b2, 3000, 3000, 750, 752);
    // conv3 + pool4 -> (B,128,187) bf16 stride 188 (512 thr, MT=2; measured best)
    conv_mma<64, 128, 2, 4, false, 512><<<dim3(6, B_), 512, sm3>>>(
        ap3, bb3, b2, b3, 750, 752, 187, 188);
    // conv4 + mean (atomic) -> feat sums (256 thr, round-6 config)
    conv4_mma_mean<<<dim3(2, B_), 256, sm4>>>(ap4, bb4, b3, feat);
    // fc + ang head -> angles (B,8)
    head_kernel<<<B_, 128>>>(feat, fc_w, fc_b, ang_w, ang_b, ang);
    // quantum sim + final MLP -> (B,5)
    qsim_kernel<<<B_, 256>>>(ang, qw, h1_w, h1_b, h2_w, h2_b, out);
}

// round 17
// speedup vs baseline: 1.1238x; 1.1238x over previous
#include <cuda_runtime.h>
#include <cuda_bf16.h>
#include <math.h>
#include <cstdint>

#define B_ 256
#define NQ_ 8
#define NL_ 2
#define NCLS_ 5

// ---------------- scratch buffers ----------------
__device__ unsigned short g_buf2[B_ * 64 * 752];    // conv2+pool out: stride 752, len 750
__device__ unsigned short g_buf3[B_ * 128 * 188];   // conv3+pool out: stride 188, len 187
__device__ float g_feat[B_ * 128];                  // conv4 sums (atomic)
__device__ float g_ang[B_ * NQ_];                   // angles

// conv1 scalar BN-folded weights: [co*28 + ci*7 + k]
__device__ float g_w1s[32 * 4 * 7];
// fragment-ordered bf16 weights: [(mt*KS2+ks2)*32+lane] -> uint4
__device__ uint4 g_ap2[4 * 16 * 32];
__device__ uint4 g_ap3[8 * 32 * 32];
__device__ uint4 g_ap4[8 * 64 * 32];
__device__ float g_bb1[32], g_bb2[64], g_bb3[128], g_bb4[128];

// ---------------- helpers ----------------
__device__ __forceinline__ unsigned pk_bf16(float lo, float hi) {
    unsigned r;
    asm("cvt.rn.bf16x2.f32 %0,%1,%2;" : "=r"(r) : "f"(hi), "f"(lo));
    return r;
}

__device__ __forceinline__ unsigned ldw(const unsigned short* row, int W, int Lh) {
    int h0 = 2 * W;
    if (W >= 0 && h0 + 1 < Lh) return ((const unsigned*)row)[W];
    unsigned lo = (h0 >= 0 && h0 < Lh) ? row[h0] : 0u;
    unsigned hi = (h0 + 1 >= 0 && h0 + 1 < Lh) ? row[h0 + 1] : 0u;
    return lo | (hi << 16);
}

__device__ __forceinline__ void mma_bf16(float* d, const uint4& a,
                                         unsigned b0, unsigned b1)
{
    asm volatile(
        "mma.sync.aligned.m16n8k16.row.col.f32.bf16.bf16.f32 "
        "{%0,%1,%2,%3},{%4,%5,%6,%7},{%8,%9},{%0,%1,%2,%3};"
        : "+f"(d[0]), "+f"(d[1]), "+f"(d[2]), "+f"(d[3])
        : "r"(a.x), "r"(a.y), "r"(a.z), "r"(a.w), "r"(b0), "r"(b1));
}

// ---------------- prepack ----------------
__device__ __forceinline__ float wget(const float* w, int co, int ci, int k,
                                      int CIN, float sc) {
    return (k < 7) ? w[(co * CIN + ci) * 7 + k] * sc : 0.0f;
}

__device__ void prep_one(const float* w, const float* cb, const float* bng,
                         const float* bnb, uint4* ap, float* bbo,
                         int CIN, int COUT, int idx)
{
    const float inv = rsqrtf(1.0f + 1e-5f);
    int KS2 = CIN / 2;
    int total = (COUT / 16) * KS2 * 32;
    if (idx < total) {
        int lane = idx & 31;
        int t = idx >> 5;
        int ks2 = t % KS2;
        int mt = t / KS2;
        int r = lane >> 2;
        int c = lane & 3;
        int co = mt * 16 + r;
        int ci0 = 2 * ks2;
        int ci1 = ci0 + 1;
        int k0 = 2 * c;
        int k1 = 2 * c + 1;
        float sc0 = bng[co] * inv;
        float sc8 = bng[co + 8] * inv;
        uint4 a;
        a.x = pk_bf16(wget(w, co,     ci0, k0, CIN, sc0), wget(w, co,     ci0, k1, CIN, sc0));
        a.y = pk_bf16(wget(w, co + 8, ci0, k0, CIN, sc8), wget(w, co + 8, ci0, k1, CIN, sc8));
        a.z = pk_bf16(wget(w, co,     ci1, k0, CIN, sc0), wget(w, co,     ci1, k1, CIN, sc0));
        a.w = pk_bf16(wget(w, co + 8, ci1, k0, CIN, sc8), wget(w, co + 8, ci1, k1, CIN, sc8));
        ap[idx] = a;
    }
    if (idx < COUT) {
        float sc = bng[idx] * inv;
        bbo[idx] = cb[idx] * sc + bnb[idx];
    }
}

__global__ void prep_all(
    const float* w1, const float* cb1, const float* g1, const float* be1,
    const float* w2, const float* cb2, const float* g2, const float* be2,
    const float* w3, const float* cb3, const float* g3, const float* be3,
    const float* w4, const float* cb4, const float* g4, const float* be4,
    float* w1s, float* bb1, uint4* ap2, float* bb2,
    uint4* ap3, float* bb3, uint4* ap4, float* bb4, float* feat)
{
    const float inv = rsqrtf(1.0f + 1e-5f);
    int idx = blockIdx.x * blockDim.x + threadIdx.x;
    // conv1 scalar folded weights
    if (idx < 32 * 28) {
        int co = idx / 28;
        int r = idx % 28;
        w1s[idx] = w1[co * 28 + r] * (g1[co] * inv);
    }
    if (idx < 32) {
        bb1[idx] = cb1[idx] * (g1[idx] * inv) + be1[idx];
    }
    prep_one(w2, cb2, g2, be2, ap2, bb2, 32, 64, idx);
    prep_one(w3, cb3, g3, be3, ap3, bb3, 64, 128, idx);
    prep_one(w4, cb4, g4, be4, ap4, bb4, 128, 128, idx);
    if (idx < B_ * 128) feat[idx] = 0.0f;
}

// ---------------- shared tile producer (dual-copy layout), bf16 gmem in ------
template<int CIN, int NWARPS>
__device__ __forceinline__ void load_tile_bf16(
    unsigned* sw, const unsigned short* inb, int tile0, int Lh, int LSTRin,
    int wid, int lane)
{
    constexpr int RS = 144;
    const int base = tile0 - 4;
    const bool interior = (base >= 0) && (base + 139 < Lh);

    for (int ci = wid; ci < CIN; ci += NWARPS) {
        const unsigned short* row = inb + ci * LSTRin;
        unsigned* d = sw + ci * RS;
        if (interior) {
            const unsigned* rw = (const unsigned*)row + (base >> 1);
            for (int j = lane; j < 69; j += 32) {
                unsigned wa = rw[j];
                unsigned wb = rw[j + 1];
                d[j]      = wa;
                d[72 + j] = (wa >> 16) | (wb << 16);
            }
        } else {
            const int W0 = base >> 1;
            for (int j = lane; j < 69; j += 32) {
                unsigned wa = ldw(row, W0 + j, Lh);
                unsigned wb = ldw(row, W0 + j + 1, Lh);
                d[j]      = wa;
                d[72 + j] = (wa >> 16) | (wb << 16);
            }
        }
    }
}

// ---------------- fused conv1+conv2 (+pool4) ----------------
// 256 threads, 2 blocks/SM. tile = 128 conv2 positions.
// Stage A: x (4ci x 148 fp32) -> smem. Stage B: scalar conv1+BN+ReLU ->
// st1 (32co x 140 fp32, positions tile0-4..tile0+135, OOR=0). Stage C: dual-copy
// bf16 tile from st1. Stage D: round-6 conv2 mainloop (MW=2,NG=4,NSW=4,KS2=16).
__global__ __launch_bounds__(256, 2) void conv12_mma(
    const float* __restrict__ w1s, const float* __restrict__ bb1,
    const uint4* __restrict__ Ap, const float* __restrict__ bb,
    const float* __restrict__ x, unsigned short* __restrict__ outp)
{
    constexpr int L1 = 3000, Lpool = 750, LSTRout = 752;
    constexpr int MT = 2, MW = 2, NSW = 4, KS2 = 16, RS = 144;
    extern __shared__ unsigned smemw[];
    unsigned* sw = smemw;                        // 32*144 = 4608 words
    float* sx  = (float*)(smemw + 4608);         // 4*148 floats
    float* st1 = sx + 4 * 148;                   // 32*140 floats

    const int b = blockIdx.y;
    const int tile0 = blockIdx.x * 128;
    const int tid = threadIdx.x;
    const int wid = tid >> 5;
    const int lane = tid & 31;

    // Stage A: input tile, positions tile0-7 .. tile0+140 (148 floats/ci)
    {
        const float* xb = x + (size_t)b * 4 * L1;
        for (int idx = tid; idx < 4 * 148; idx += 256) {
            int ci = idx / 148;
            int j = idx - ci * 148;
            int p = tile0 - 7 + j;
            sx[idx] = (p >= 0 && p < L1) ? xb[ci * L1 + p] : 0.0f;
        }
    }
    __syncthreads();

    // Stage B: scalar conv1 -> st1. 448 items = 32 co x 14 strips of 10 pos.
    for (int it = tid; it < 448; it += 256) {
        int co = it / 14;
        int s = it - co * 14;
        int u0 = s * 10;
        float acc[10];
        #pragma unroll
        for (int u = 0; u < 10; u++) acc[u] = 0.0f;
        #pragma unroll
        for (int ci = 0; ci < 4; ci++) {
            const float* wr = w1s + co * 28 + ci * 7;
            float xv[16];
            #pragma unroll
            for (int t = 0; t < 16; t++) xv[t] = sx[ci * 148 + u0 + t];
            #pragma unroll
            for (int k = 0; k < 7; k++) {
                float wk = wr[k];
                #pragma unroll
                for (int u = 0; u < 10; u++) acc[u] = fmaf(wk, xv[u + k], acc[u]);
            }
        }
        float bbv = bb1[co];
        #pragma unroll
        for (int u = 0; u < 10; u++) {
            int p1 = tile0 - 4 + u0 + u;
            st1[co * 140 + u0 + u] =
                (p1 >= 0 && p1 < L1) ? fmaxf(acc[u] + bbv, 0.0f) : 0.0f;
        }
    }
    __syncthreads();

    // Stage C: dual-copy bf16 tile from st1 (base half = tile0-4 = st1 idx 0)
    for (int ci = wid; ci < 32; ci += 8) {
        const float* row = st1 + ci * 140;
        unsigned* d = sw + ci * RS;
        for (int j = lane; j < 69; j += 32) {
            float v0 = row[2 * j];
            float v1 = row[2 * j + 1];
            float v2 = row[2 * j + 2];
            d[j]      = pk_bf16(v0, v1);
            d[72 + j] = pk_bf16(v1, v2);
        }
    }
    __syncthreads();

    // Stage D: conv2 mainloop (round-6 config) + pool epilogue
    const int mw = wid % MW;
    const int ng = wid / MW;
    const int ng_off = ng * (NSW * 8);
    const int gid = lane >> 2;
    const int tid4 = lane & 3;
    const int h0 = ng_off + gid + 2 * tid4 + 1;
    const int off0 = (h0 >> 1) + ((h0 & 1) ? 72 : 0);

    float acc[MT][NSW][4] = {};
    const uint4* A0 = Ap + (size_t)((mw * MT + 0) * KS2) * 32 + lane;
    const uint4* A1 = Ap + (size_t)((mw * MT + 1) * KS2) * 32 + lane;
    uint4 a0 = A0[0];
    uint4 a1 = A1[0];

    for (int ks2 = 0; ks2 < KS2; ks2++) {
        const int nk = (ks2 + 1 < KS2) ? ks2 + 1 : ks2;
        uint4 n0 = A0[nk * 32];
        uint4 n1 = A1[nk * 32];
        const unsigned* s0 = sw + (2 * ks2) * RS + off0;
        #pragma unroll
        for (int ns = 0; ns < NSW; ns++) {
            unsigned b0 = s0[ns * 4];
            unsigned b1 = s0[RS + ns * 4];
            mma_bf16(acc[0][ns], a0, b0, b1);
            mma_bf16(acc[1][ns], a1, b0, b1);
        }
        a0 = n0;
        a1 = n1;
    }

    #pragma unroll
    for (int m = 0; m < MT; m++) {
        const int mt = mw * MT + m;
        const int co0 = mt * 16 + gid;
        const int co1 = co0 + 8;
        const float bv0 = bb[co0];
        const float bv1 = bb[co1];
        #pragma unroll
        for (int ns = 0; ns < NSW; ns++) {
            float m0 = fmaxf(fmaxf(acc[m][ns][0], acc[m][ns][1]) + bv0, 0.f);
            float m1 = fmaxf(fmaxf(acc[m][ns][2], acc[m][ns][3]) + bv1, 0.f);
            m0 = fmaxf(m0, __shfl_xor_sync(0xffffffffu, m0, 1));
            m1 = fmaxf(m1, __shfl_xor_sync(0xffffffffu, m1, 1));
            if (!(lane & 1)) {
                int pi = ((tile0 + ng_off + ns * 8) >> 2) + (tid4 >> 1);
                if (pi < Lpool) {
                    __nv_bfloat16 h0b = __float2bfloat16_rn(m0);
                    __nv_bfloat16 h1b = __float2bfloat16_rn(m1);
                    outp[((size_t)b * 64 + co0) * LSTRout + pi] = *(unsigned short*)&h0b;
                    outp[((size_t)b * 64 + co1) * LSTRout + pi] = *(unsigned short*)&h1b;
                }
            }
        }
    }
}

// ---------------- conv3: implicit GEMM (512 thr, MT=2; measured best) --------
template<int CIN, int COUT, int MT, int MODE, int NT>
__global__ __launch_bounds__(NT, 2) void conv_mma(
    const uint4* __restrict__ Ap, const float* __restrict__ bb,
    const unsigned short* __restrict__ in_, unsigned short* __restrict__ out_,
    int Lh, int LSTRin, int Lout, int LSTRout)
{
    constexpr int NWARPS = NT / 32;
    constexpr int MW  = COUT / (16 * MT);
    constexpr int NG  = NWARPS / MW;
    constexpr int NSW = 16 / NG;
    constexpr int KS2 = CIN / 2;
    constexpr int RS  = 144;
    extern __shared__ unsigned sw[];

    const int b = blockIdx.y;
    const int tile0 = blockIdx.x * 128;
    const int tid = threadIdx.x;
    const int wid = tid >> 5;
    const int lane = tid & 31;

    load_tile_bf16<CIN, NWARPS>(sw, in_ + (size_t)b * CIN * LSTRin,
                                tile0, Lh, LSTRin, wid, lane);
    __syncthreads();

    const int mw = wid % MW;
    const int ng = wid / MW;
    const int ng_off = ng * (NSW * 8);
    const int gid = lane >> 2;
    const int tid4 = lane & 3;
    const int h0 = ng_off + gid + 2 * tid4 + 1;
    const int off0 = (h0 >> 1) + ((h0 & 1) ? 72 : 0);

    float acc[MT][NSW][4] = {};
    const uint4* A0 = Ap + (size_t)((mw * MT + 0) * KS2) * 32 + lane;
    const uint4* A1 = Ap + (size_t)((mw * MT + 1) * KS2) * 32 + lane;
    uint4 a0 = A0[0];
    uint4 a1 = A1[0];

    for (int ks2 = 0; ks2 < KS2; ks2++) {
        const int nk = (ks2 + 1 < KS2) ? ks2 + 1 : ks2;
        uint4 n0 = A0[nk * 32];
        uint4 n1 = A1[nk * 32];
        const unsigned* s0 = sw + (2 * ks2) * RS + off0;
        #pragma unroll
        for (int ns = 0; ns < NSW; ns++) {
            unsigned b0 = s0[ns * 4];
            unsigned b1 = s0[RS + ns * 4];
            mma_bf16(acc[0][ns], a0, b0, b1);
            mma_bf16(acc[1][ns], a1, b0, b1);
        }
        a0 = n0;
        a1 = n1;
    }

    #pragma unroll
    for (int m = 0; m < MT; m++) {
        const int mt = mw * MT + m;
        const int co0 = mt * 16 + gid;
        const int co1 = co0 + 8;
        const float bv0 = bb[co0];
        const float bv1 = bb[co1];
        #pragma unroll
        for (int ns = 0; ns < NSW; ns++) {
            float m0 = fmaxf(fmaxf(acc[m][ns][0], acc[m][ns][1]) + bv0, 0.f);
            float m1 = fmaxf(fmaxf(acc[m][ns][2], acc[m][ns][3]) + bv1, 0.f);
            m0 = fmaxf(m0, __shfl_xor_sync(0xffffffffu, m0, 1));
            m1 = fmaxf(m1, __shfl_xor_sync(0xffffffffu, m1, 1));
            if (!(lane & 1)) {
                int pi = ((tile0 + ng_off + ns * 8) >> 2) + (tid4 >> 1);
                if (pi < Lout) {
                    __nv_bfloat16 h0b = __float2bfloat16_rn(m0);
                    __nv_bfloat16 h1b = __float2bfloat16_rn(m1);
                    out_[((size_t)b * COUT + co0) * LSTRout + pi] = *(unsigned short*)&h0b;
                    out_[((size_t)b * COUT + co1) * LSTRout + pi] = *(unsigned short*)&h1b;
                }
            }
        }
    }
}

// ---------------- conv4 + BN + ReLU + mean (round-6 config: 256 thr) ---------
__global__ __launch_bounds__(256, 2) void conv4_mma_mean(
    const uint4* __restrict__ Ap, const float* __restrict__ bb,
    const unsigned short* __restrict__ in, float* __restrict__ feat)
{
    constexpr int CIN = 128, KS2 = 64, NSW = 8;
    constexpr int Lc = 187, LSTR = 188, RS = 144;
    extern __shared__ unsigned sw[];

    const int b = blockIdx.y;
    const int tile0 = blockIdx.x * 128;
    const int tid = threadIdx.x;
    const int wid = tid >> 5;
    const int lane = tid & 31;

    load_tile_bf16<CIN, 8>(sw, in + (size_t)b * CIN * LSTR,
                           tile0, Lc, LSTR, wid, lane);
    __syncthreads();

    const int mw = wid % 4;
    const int ng = wid / 4;
    const int mt0 = mw * 2;
    const int mt1 = mt0 + 1;
    const int ng_off = ng * (NSW * 8);
    const int gid = lane >> 2;
    const int tid4 = lane & 3;
    const int h0 = ng_off + gid + 2 * tid4 + 1;
    const int off0 = (h0 >> 1) + ((h0 & 1) ? 72 : 0);

    float acc[2][NSW][4] = {};
    const uint4* A0 = Ap + (size_t)(mt0 * KS2) * 32 + lane;
    const uint4* A1 = Ap + (size_t)(mt1 * KS2) * 32 + lane;
    uint4 a0 = A0[0];
    uint4 a1 = A1[0];

    for (int ks2 = 0; ks2 < KS2; ks2++) {
        const int nk = (ks2 + 1 < KS2) ? ks2 + 1 : ks2;
        uint4 n0 = A0[nk * 32];
        uint4 n1 = A1[nk * 32];
        const unsigned* s0 = sw + (2 * ks2) * RS + off0;
        #pragma unroll
        for (int ns = 0; ns < NSW; ns++) {
            unsigned b0 = s0[ns * 4];
            unsigned b1 = s0[RS + ns * 4];
            mma_bf16(acc[0][ns], a0, b0, b1);
            mma_bf16(acc[1][ns], a1, b0, b1);
        }
        a0 = n0;
        a1 = n1;
    }

    #pragma unroll
    for (int m = 0; m < 2; m++) {
        const int mt = (m == 0) ? mt0 : mt1;
        const int co0 = mt * 16 + gid;
        const int co1 = co0 + 8;
        const float bv0 = bb[co0];
        const float bv1 = bb[co1];
        float s0 = 0.f, s1 = 0.f;
        #pragma unroll
        for (int ns = 0; ns < NSW; ns++) {
            int pos = tile0 + ng_off + ns * 8 + 2 * tid4;
            if (pos < Lc) {
                s0 += fmaxf(acc[m][ns][0] + bv0, 0.f);
                s1 += fmaxf(acc[m][ns][2] + bv1, 0.f);
            }
            if (pos + 1 < Lc) {
                s0 += fmaxf(acc[m][ns][1] + bv0, 0.f);
                s1 += fmaxf(acc[m][ns][3] + bv1, 0.f);
            }
        }
        s0 += __shfl_xor_sync(0xffffffffu, s0, 1);
        s0 += __shfl_xor_sync(0xffffffffu, s0, 2);
        s1 += __shfl_xor_sync(0xffffffffu, s1, 1);
        s1 += __shfl_xor_sync(0xffffffffu, s1, 2);
        if ((lane & 3) == 0) {
            atomicAdd(feat + b * 128 + co0, s0);
            atomicAdd(feat + b * 128 + co1, s1);
        }
    }
}

// ---------------- fc(128->128)+relu, ang(128->8), angles = pi*tanh ----------
__global__ void head_kernel(const float* __restrict__ feat,
                            const float* __restrict__ fcw, const float* __restrict__ fcb,
                            const float* __restrict__ angw, const float* __restrict__ angb,
                            float* __restrict__ ang)
{
    int b = blockIdx.x;
    int tid = threadIdx.x;   // 128 threads
    __shared__ float f[128];
    __shared__ float h[128];
    f[tid] = feat[b * 128 + tid] * (1.0f / 187.0f);
    __syncthreads();
    float a = fcb[tid];
    const float* wr = fcw + tid * 128;
    #pragma unroll 8
    for (int k = 0; k < 128; k++) a = fmaf(wr[k], f[k], a);
    h[tid] = fmaxf(a, 0.f);
    __syncthreads();
    if (tid < NQ_) {
        float r = angb[tid];
        const float* ar = angw + tid * 128;
        #pragma unroll 8
        for (int k = 0; k < 128; k++) r = fmaf(ar[k], h[k], r);
        ang[b * NQ_ + tid] = 3.14159265358979323846f * tanhf(r);
    }
}

// ---------------- 8-qubit statevector sim + PauliZ + MLP head ----------------
__device__ __forceinline__ float2 cmul(float2 a, float2 b) {
    return make_float2(a.x * b.x - a.y * b.y, a.x * b.y + a.y * b.x);
}
__device__ __forceinline__ float2 cadd(float2 a, float2 b) {
    return make_float2(a.x + b.x, a.y + b.y);
}

__global__ void qsim_kernel(const float* __restrict__ ang, const float* __restrict__ qw,
                            const float* __restrict__ h1w, const float* __restrict__ h1b,
                            const float* __restrict__ h2w, const float* __restrict__ h2b,
                            float* __restrict__ out)
{
    int b = blockIdx.x;
    int i = threadIdx.x;   // 256 threads
    __shared__ float2 st[256];
    st[i] = make_float2(i == 0 ? 1.f : 0.f, 0.f);
    __syncthreads();

    for (int wq = 0; wq < NQ_; wq++) {
        int m = 1 << (7 - wq);
        float a = 0.5f * ang[b * NQ_ + wq];
        float c = cosf(a);
        float s = sinf(a);
        if ((i & m) == 0) {
            float2 a0 = st[i];
            float2 a1 = st[i | m];
            st[i]     = make_float2(c * a0.x - s * a1.x, c * a0.y - s * a1.y);
            st[i | m] = make_float2(s * a0.x + c * a1.x, s * a0.y + c * a1.y);
        }
        __syncthreads();
    }

    for (int l = 0; l < NL_; l++) {
        for (int wq = 0; wq < NQ_; wq++) {
            int m = 1 << (7 - wq);
            const float* p = qw + (l * NQ_ + wq) * 3;
            float phi = p[0];
            float th = p[1];
            float om = p[2];
            float cm = cosf(0.5f * th);
            float sm = sinf(0.5f * th);
            float hpo = 0.5f * (phi + om);
            float hpm = 0.5f * (phi - om);
            float2 m00 = make_float2( cm * cosf(hpo), -cm * sinf(hpo));
            float2 m01 = make_float2(-sm * cosf(hpm), -sm * sinf(hpm));
            float2 m10 = make_float2( sm * cosf(hpm), -sm * sinf(hpm));
            float2 m11 = make_float2( cm * cosf(hpo),  cm * sinf(hpo));
            if ((i & m) == 0) {
                float2 a0 = st[i];
                float2 a1 = st[i | m];
                st[i]     = cadd(cmul(m00, a0), cmul(m01, a1));
                st[i | m] = cadd(cmul(m10, a0), cmul(m11, a1));
            }
            __syncthreads();
        }
        int r = (l % (NQ_ - 1)) + 1;
        for (int q = 0; q < NQ_; q++) {
            int cq = q;
            int tq = (q + r) & 7;
            int mc = 1 << (7 - cq);
            int mt = 1 << (7 - tq);
            if ((i & mc) && !(i & mt)) {
                float2 tmp = st[i];
                st[i] = st[i | mt];
                st[i | mt] = tmp;
            }
            __syncthreads();
        }
    }

    float pv = st[i].x * st[i].x + st[i].y * st[i].y;
    __shared__ float zpart[8][8];
    int warp = i >> 5;
    int lane = i & 31;
    #pragma unroll
    for (int wq = 0; wq < NQ_; wq++) {
        float v = ((i >> (7 - wq)) & 1) ? -pv : pv;
        #pragma unroll
        for (int o = 16; o; o >>= 1) v += __shfl_down_sync(0xffffffffu, v, o);
        if (lane == 0) zpart[warp][wq] = v;
    }
    __syncthreads();

    __shared__ float z[NQ_];
    if (i < NQ_) {
        float s = 0.f;
        #pragma unroll
        for (int w = 0; w < 8; w++) s += zpart[w][i];
        z[i] = s;
    }
    __syncthreads();

    __shared__ float h1[64];
    if (i < 64) {
        float a = h1b[i];
        #pragma unroll
        for (int k = 0; k < NQ_; k++) a = fmaf(h1w[i * NQ_ + k], z[k], a);
        h1[i] = fmaxf(a, 0.f);
    }
    __syncthreads();

    if (i < NCLS_) {
        float a = h2b[i];
        #pragma unroll 8
        for (int k = 0; k < 64; k++) a = fmaf(h2w[i * 64 + k], h1[k], a);
        out[b * NCLS_ + i] = a;
    }
}

// ---------------- launch ----------------
extern "C" void kernel_launch(void* const* d_in, const int* in_sizes, int n_in,
                              void* d_out, int out_size)
{
    const float* x       = (const float*)d_in[0];
    const float* conv1_w = (const float*)d_in[1];
    const float* conv1_b = (const float*)d_in[2];
    const float* bn1_g   = (const float*)d_in[3];
    const float* bn1_b   = (const float*)d_in[4];
    const float* conv2_w = (const float*)d_in[5];
    const float* conv2_b = (const float*)d_in[6];
    const float* bn2_g   = (const float*)d_in[7];
    const float* bn2_b   = (const float*)d_in[8];
    const float* conv3_w = (const float*)d_in[9];
    const float* conv3_b = (const float*)d_in[10];
    const float* bn3_g   = (const float*)d_in[11];
    const float* bn3_b   = (const float*)d_in[12];
    const float* conv4_w = (const float*)d_in[13];
    const float* conv4_b = (const float*)d_in[14];
    const float* bn4_g   = (const float*)d_in[15];
    const float* bn4_b   = (const float*)d_in[16];
    const float* fc_w    = (const float*)d_in[17];
    const float* fc_b    = (const float*)d_in[18];
    const float* ang_w   = (const float*)d_in[19];
    const float* ang_b   = (const float*)d_in[20];
    const float* qw      = (const float*)d_in[21];
    const float* h1_w    = (const float*)d_in[22];
    const float* h1_b    = (const float*)d_in[23];
    const float* h2_w    = (const float*)d_in[24];
    const float* h2_b    = (const float*)d_in[25];
    float* out = (float*)d_out;

    void* pv = 0;
    cudaGetSymbolAddress(&pv, g_buf2);  unsigned short* b2 = (unsigned short*)pv;
    cudaGetSymbolAddress(&pv, g_buf3);  unsigned short* b3 = (unsigned short*)pv;
    cudaGetSymbolAddress(&pv, g_feat);  float* feat = (float*)pv;
    cudaGetSymbolAddress(&pv, g_ang);   float* ang = (float*)pv;
    cudaGetSymbolAddress(&pv, g_w1s);   float* w1s = (float*)pv;
    cudaGetSymbolAddress(&pv, g_ap2);   uint4* ap2 = (uint4*)pv;
    cudaGetSymbolAddress(&pv, g_ap3);   uint4* ap3 = (uint4*)pv;
    cudaGetSymbolAddress(&pv, g_ap4);   uint4* ap4 = (uint4*)pv;
    cudaGetSymbolAddress(&pv, g_bb1);   float* bb1 = (float*)pv;
    cudaGetSymbolAddress(&pv, g_bb2);   float* bb2 = (float*)pv;
    cudaGetSymbolAddress(&pv, g_bb3);   float* bb3 = (float*)pv;
    cudaGetSymbolAddress(&pv, g_bb4);   float* bb4 = (float*)pv;

    prep_all<<<128, 256>>>(
        conv1_w, conv1_b, bn1_g, bn1_b, conv2_w, conv2_b, bn2_g, bn2_b,
        conv3_w, conv3_b, bn3_g, bn3_b, conv4_w, conv4_b, bn4_g, bn4_b,
        w1s, bb1, ap2, bb2, ap3, bb3, ap4, bb4, feat);

    size_t sm12 = (size_t)(4608 + 592 + 4480) * 4;   // 38720 B
    size_t sm3  = (size_t)64  * 144 * 4;             // 36864
    size_t sm4  = (size_t)128 * 144 * 4;             // 73728 > 48KB

    cudaFuncSetAttribute(conv4_mma_mean,
                         cudaFuncAttributeMaxDynamicSharedMemorySize, (int)sm4);

    // fused conv1+conv2+pool4: x (B,4,3000) fp32 -> (B,64,750) bf16 stride 752
    conv12_mma<<<dim3(24, B_), 256, sm12>>>(w1s, bb1, ap2, bb2, x, b2);
    // conv3 + pool4 -> (B,128,187) bf16 stride 188 (512 thr, MT=2)
    conv_mma<64, 128, 2, 4, 512><<<dim3(6, B_), 512, sm3>>>(
        ap3, bb3, b2, b3, 750, 752, 187, 188);
    // conv4 + mean (atomic) -> feat sums (256 thr)
    conv4_mma_mean<<<dim3(2, B_), 256, sm4>>>(ap4, bb4, b3, feat);
    // fc + ang head -> angles (B,8)
    head_kernel<<<B_, 128>>>(feat, fc_w, fc_b, ang_w, ang_b, ang);
    // quantum sim + final MLP -> (B,5)
    qsim_kernel<<<B_, 256>>>(ang, qw, h1_w, h1_b, h2_w, h2_b, out);
}